// round 12
// baseline (speedup 1.0000x reference)
#include <cuda_runtime.h>
#include <cuda_fp16.h>
#include <math.h>

// ============================================================================
// MLP3D via fp16 mma.sync.m16n8k16.
// L0: A fp16, B fp16 hi+lo (2 products). L1/L2/parts: plain fp16 (1 product).
// Block = 128 points, 512 threads = 16 warps tiled 4(M)x4(N), warp = m32xn64
// => acc 64 regs/thread => 128-reg budget => 4 warps/SMSP (occ 25%).
// B fragments pre-packed in fragment order, read from L2/L1 via LDG with
// one-k-tile ping-pong prefetch; A via single-buffered ldmatrix.
// Output: out[0..n) = occ ; out[n..5n) = part_class [N,4] row-major.
// ============================================================================

#define LDA 264
#define U_L1 0
#define U_L2 16384
#define U_PT 32768

__device__ uint4 gW4[4096];      // L0: hi.k01,hi.k89,lo.k01,lo.k89
__device__ uint2 gW2[36864];     // L1/L2/parts: hi only

#define SC_OFF (128 * LDA * 2)             // 67584 (sActH only, fp16)
#define SMEM_BYTES (SC_OFF + 1800 * 4)

typedef unsigned u32;

__device__ __forceinline__ u32 pack2h(__half a, __half b) {
    return (u32)__half_as_ushort(a) | ((u32)__half_as_ushort(b) << 16);
}
__device__ __forceinline__ void mma16816(float d[4], const u32 a[4],
                                         u32 b0, u32 b1) {
    asm volatile(
        "mma.sync.aligned.m16n8k16.row.col.f32.f16.f16.f32 "
        "{%0,%1,%2,%3},{%4,%5,%6,%7},{%8,%9},{%0,%1,%2,%3};"
        : "+f"(d[0]), "+f"(d[1]), "+f"(d[2]), "+f"(d[3])
        : "r"(a[0]), "r"(a[1]), "r"(a[2]), "r"(a[3]), "r"(b0), "r"(b1));
}
__device__ __forceinline__ void ldsm4(u32 r[4], const __half* p) {
    u32 a = (u32)__cvta_generic_to_shared(p);
    asm volatile("ldmatrix.sync.aligned.m8n8.x4.shared.b16 {%0,%1,%2,%3}, [%4];"
                 : "=r"(r[0]), "=r"(r[1]), "=r"(r[2]), "=r"(r[3]) : "r"(a));
}
__device__ __forceinline__ void lda2(u32 (&a)[2][4], const __half* aP, int kt) {
    ldsm4(a[0], aP + kt * 16);
    ldsm4(a[1], aP + 16 * LDA + kt * 16);
}

// ---------------------------------------------------------------------------
__global__ void prep_kernel(const float* __restrict__ W0,
                            const float* __restrict__ W1,
                            const float* __restrict__ W2) {
    int idx = blockIdx.x * blockDim.x + threadIdx.x;
    if (idx >= 40960) return;

    if (idx < 4096) {                        // L0: hi+lo uint4, Kact=63
        int kt = idx >> 10, r = idx & 1023, tig = r >> 8, nn = r & 255;
        int k0 = 16 * kt + 2 * tig;
        int ks[4] = {k0, k0 + 1, k0 + 8, k0 + 9};
        __half h[4], l[4];
#pragma unroll
        for (int i = 0; i < 4; ++i) {
            float v = (ks[i] < 63) ? W0[ks[i] * 256 + nn] : 0.f;
            h[i] = __float2half_rn(v);
            l[i] = __float2half_rn(v - __half2float(h[i]));
        }
        gW4[idx] = make_uint4(pack2h(h[0], h[1]), pack2h(h[2], h[3]),
                              pack2h(l[0], l[1]), pack2h(l[2], l[3]));
        return;
    }
    int u = idx - 4096;
    const float* W; int kt, tig, nn, rowOff = 0, colOff = 0;
    if (u < 16384)       { W = W1;
        kt = u >> 10; int r = u & 1023; tig = r >> 8; nn = r & 255; }
    else if (u < 32768)  { W = W2; int v = u - 16384;
        kt = v >> 10; int r = v & 1023; tig = r >> 8; nn = r & 255; }
    else {                 W = W1; int v = u - 32768;
        int p = v >> 10; int r = v & 1023;
        kt = r >> 8; tig = (r >> 6) & 3; nn = r & 63;
        rowOff = 64 * p; colOff = 64 * p; }
    int k0 = 16 * kt + 2 * tig;
    int ks[4] = {k0, k0 + 1, k0 + 8, k0 + 9};
    __half h[4];
#pragma unroll
    for (int i = 0; i < 4; ++i)
        h[i] = __float2half_rn(W[(rowOff + ks[i]) * 256 + colOff + nn]);
    gW2[u] = make_uint2(pack2h(h[0], h[1]), pack2h(h[2], h[3]));
}

// ---------------------------------------------------------------------------
__device__ __forceinline__ void mma_block1(
    float (&acc)[2][8][4], const u32 (&a)[2][4], const uint2 (&b)[8])
{
#pragma unroll
    for (int nt = 0; nt < 8; ++nt)
#pragma unroll
        for (int mt = 0; mt < 2; ++mt)
            mma16816(acc[mt][nt], a[mt], b[nt].x, b[nt].y);
}

// L0: 2-product (hi then lo), KT=4, B = gW4 (single-buffered to cap regs).
__device__ __forceinline__ void trunk_L0(
    float (&acc)[2][8][4], const __half* aP, int tig, int gid, int wn)
{
#pragma unroll
    for (int mt = 0; mt < 2; ++mt)
#pragma unroll
        for (int nt = 0; nt < 8; ++nt)
            acc[mt][nt][0] = acc[mt][nt][1] = acc[mt][nt][2] = acc[mt][nt][3] = 0.f;
    const uint4* __restrict__ gB = gW4 + tig * 256 + wn * 64 + gid;
    uint4 bc[8];
    u32 a[2][4];
#pragma unroll 1
    for (int kt = 0; kt < 4; ++kt) {
#pragma unroll
        for (int nt = 0; nt < 8; ++nt) bc[nt] = gB[kt * 1024 + nt * 8];
        lda2(a, aP, kt);
#pragma unroll
        for (int nt = 0; nt < 8; ++nt)
#pragma unroll
            for (int mt = 0; mt < 2; ++mt)
                mma16816(acc[mt][nt], a[mt], bc[nt].x, bc[nt].y);
#pragma unroll
        for (int nt = 0; nt < 8; ++nt)
#pragma unroll
            for (int mt = 0; mt < 2; ++mt)
                mma16816(acc[mt][nt], a[mt], bc[nt].z, bc[nt].w);
    }
}

// 1-product trunk layer (L1/L2), B ping-pong prefetch, A single-buffer.
__device__ __forceinline__ void trunk_1p(
    float (&acc)[2][8][4], int ubase, const __half* aP,
    int tig, int gid, int wn)
{
#pragma unroll
    for (int mt = 0; mt < 2; ++mt)
#pragma unroll
        for (int nt = 0; nt < 8; ++nt)
            acc[mt][nt][0] = acc[mt][nt][1] = acc[mt][nt][2] = acc[mt][nt][3] = 0.f;
    const uint2* __restrict__ gB = gW2 + ubase + tig * 256 + wn * 64 + gid;
    uint2 bc[8], bn[8];
    u32 a[2][4];
#pragma unroll
    for (int nt = 0; nt < 8; ++nt) bc[nt] = gB[nt * 8];
#pragma unroll 1
    for (int kt = 0; kt < 16; kt += 2) {
#pragma unroll
        for (int nt = 0; nt < 8; ++nt) bn[nt] = gB[(kt + 1) * 1024 + nt * 8];
        lda2(a, aP, kt);
        mma_block1(acc, a, bc);
        if (kt + 2 < 16) {
#pragma unroll
            for (int nt = 0; nt < 8; ++nt) bc[nt] = gB[(kt + 2) * 1024 + nt * 8];
        }
        lda2(a, aP, kt + 1);
        mma_block1(acc, a, bn);
    }
}

// ---------------------------------------------------------------------------
__global__ void __launch_bounds__(512, 1)
mlp3d_main(const float* __restrict__ coords,
           const float* __restrict__ b0g, const float* __restrict__ b1g,
           const float* __restrict__ b2g, const float* __restrict__ Woccg,
           const float* __restrict__ boccg, const float* __restrict__ Wcg,
           const float* __restrict__ bcg, float* __restrict__ out, int nTot)
{
    extern __shared__ char smem[];
    __half* sActH = (__half*)smem;
    float* sC = (float*)(smem + SC_OFF);
    float *sB0 = sC, *sB1 = sC + 256, *sB2 = sC + 512;
    float *sWocc = sC + 768, *sWcS = sC + 1024, *sEx = sC + 1280;
    float *sRed = sC + 1288;                      // 512 floats

    const int t = threadIdx.x, wid = t >> 5, lane = t & 31;
    const int tig = lane & 3, gid = lane >> 2;
    const int wm = wid & 3, wn = wid >> 2;        // 4(M) x 4(N)
    const int pt0 = blockIdx.x * 128;

    if (t < 256) {
        sB0[t] = b0g[t]; sB1[t] = b1g[t]; sB2[t] = b2g[t]; sWocc[t] = Woccg[t];
        int p = t >> 6, j = t & 63; sWcS[t] = Wcg[p * 256 + p * 64 + j];
        if (t < 4) sEx[t] = bcg[t];
        if (t == 4) sEx[4] = boccg[0];
    }

    // ---- embedding (cols 0..62, col 63 zero) ----
    if (t < 128) sActH[t * LDA + 63] = __float2half(0.f);
    if (t < 384) {
        int pt = t / 3, d = t % 3;
        float c = (pt0 + pt < nTot) ? coords[(pt0 + pt) * 3 + d] : 0.f;
        __half* rh = sActH + pt * LDA;
        rh[d] = __float2half_rn(c);
        float ang = c;
#pragma unroll
        for (int f = 0; f < 10; ++f) {
            float s, co; sincosf(ang, &s, &co);
            rh[3 + 6 * f + d] = __float2half_rn(s);
            rh[6 + 6 * f + d] = __float2half_rn(co);
            ang += ang;
        }
    }
    __syncthreads();

    const int lr = lane & 7, sel = lane >> 3;
    const int rowc = ((sel & 1) << 3) + lr, acol = (sel >> 1) << 3;
    const __half* aP = sActH + (wm * 32 + rowc) * LDA + acol;   // trunk: m32 tile
    // parts mapping: warp = (rowgroup rg, part p)
    const int prt = wid & 3, rg = wid >> 2;
    const __half* aPp = sActH + (rg * 32 + rowc) * LDA + acol;

    float acc[2][8][4];

    // ======== L0: x = emb @ W0 + b0 (no relu, 2-product) ========
    trunk_L0(acc, aP, tig, gid, wn);
    __syncthreads();
#pragma unroll
    for (int mt = 0; mt < 2; ++mt) {
        int row = wm * 32 + mt * 16 + gid;
#pragma unroll
        for (int nt = 0; nt < 8; ++nt) {
            int n = (wn * 8 + nt) * 8 + 2 * tig;
            float ba = sB0[n], bb = sB0[n + 1];
            *(u32*)(sActH + row * LDA + n) =
                pack2h(__float2half_rn(acc[mt][nt][0] + ba),
                       __float2half_rn(acc[mt][nt][1] + bb));
            *(u32*)(sActH + (row + 8) * LDA + n) =
                pack2h(__float2half_rn(acc[mt][nt][2] + ba),
                       __float2half_rn(acc[mt][nt][3] + bb));
        }
    }
    __syncthreads();

    // ======== part branches: warp (rg, prt) does rows rg*32..+32 of part prt
    {
        const uint2* __restrict__ gBp =
            gW2 + U_PT + prt * 1024 + tig * 64 + gid;
        float (&pacc)[2][8][4] = acc;
#pragma unroll
        for (int mt = 0; mt < 2; ++mt)
#pragma unroll
            for (int nt = 0; nt < 8; ++nt)
                pacc[mt][nt][0] = pacc[mt][nt][1] =
                pacc[mt][nt][2] = pacc[mt][nt][3] = 0.f;
        uint2 pc[8], pn[8];
        u32 pa[2][4];
#pragma unroll
        for (int nt = 0; nt < 8; ++nt) pc[nt] = gBp[nt * 8];
#pragma unroll
        for (int kt = 0; kt < 4; ++kt) {
            if (kt < 3) {
#pragma unroll
                for (int nt = 0; nt < 8; ++nt)
                    pn[nt] = gBp[(kt + 1) * 256 + nt * 8];
            }
            lda2(pa, aPp + prt * 64, kt);
#pragma unroll
            for (int nt = 0; nt < 8; ++nt)
#pragma unroll
                for (int mt = 0; mt < 2; ++mt)
                    mma16816(pacc[mt][nt], pa[mt], pc[nt].x, pc[nt].y);
            if (kt < 3) {
#pragma unroll
                for (int nt = 0; nt < 8; ++nt) pc[nt] = pn[nt];
            }
        }
#pragma unroll
        for (int mt = 0; mt < 2; ++mt) {
            float sA = 0.f, sBv = 0.f;
#pragma unroll
            for (int nt = 0; nt < 8; ++nt) {
                int n = nt * 8 + 2 * tig;
                float ba = sB1[64 * prt + n], bb2 = sB1[64 * prt + n + 1];
                float wa = sWcS[64 * prt + n], wb = sWcS[64 * prt + n + 1];
                sA += fmaxf(pacc[mt][nt][0] + ba, 0.f) * wa
                    + fmaxf(pacc[mt][nt][1] + bb2, 0.f) * wb;
                sBv += fmaxf(pacc[mt][nt][2] + ba, 0.f) * wa
                     + fmaxf(pacc[mt][nt][3] + bb2, 0.f) * wb;
            }
            sA += __shfl_xor_sync(0xffffffffu, sA, 1);
            sA += __shfl_xor_sync(0xffffffffu, sA, 2);
            sBv += __shfl_xor_sync(0xffffffffu, sBv, 1);
            sBv += __shfl_xor_sync(0xffffffffu, sBv, 2);
            if (tig == 0) {
                int m = rg * 32 + mt * 16 + gid;
                if (pt0 + m < nTot)
                    out[nTot + (pt0 + m) * 4 + prt] = sA + sEx[prt];
                if (pt0 + m + 8 < nTot)
                    out[nTot + (pt0 + m + 8) * 4 + prt] = sBv + sEx[prt];
            }
        }
    }

    // ======== L1: h = relu(x @ W1 + b1), in-place (1-product) ========
    trunk_1p(acc, U_L1, aP, tig, gid, wn);
    __syncthreads();
#pragma unroll
    for (int mt = 0; mt < 2; ++mt) {
        int row = wm * 32 + mt * 16 + gid;
#pragma unroll
        for (int nt = 0; nt < 8; ++nt) {
            int n = (wn * 8 + nt) * 8 + 2 * tig;
            float ba = sB1[n], bb = sB1[n + 1];
            *(u32*)(sActH + row * LDA + n) =
                pack2h(__float2half_rn(fmaxf(acc[mt][nt][0] + ba, 0.f)),
                       __float2half_rn(fmaxf(acc[mt][nt][1] + bb, 0.f)));
            *(u32*)(sActH + (row + 8) * LDA + n) =
                pack2h(__float2half_rn(fmaxf(acc[mt][nt][2] + ba, 0.f)),
                       __float2half_rn(fmaxf(acc[mt][nt][3] + bb, 0.f)));
        }
    }
    __syncthreads();

    // ======== L2 + fused occ head (1-product) ========
    trunk_1p(acc, U_L2, aP, tig, gid, wn);
#pragma unroll
    for (int mt = 0; mt < 2; ++mt) {
        float oA = 0.f, oB = 0.f;
#pragma unroll
        for (int nt = 0; nt < 8; ++nt) {
            int n = (wn * 8 + nt) * 8 + 2 * tig;
            float ba = sB2[n], bb = sB2[n + 1];
            float wa = sWocc[n], wb = sWocc[n + 1];
            oA += fmaxf(acc[mt][nt][0] + ba, 0.f) * wa
                + fmaxf(acc[mt][nt][1] + bb, 0.f) * wb;
            oB += fmaxf(acc[mt][nt][2] + ba, 0.f) * wa
                + fmaxf(acc[mt][nt][3] + bb, 0.f) * wb;
        }
        oA += __shfl_xor_sync(0xffffffffu, oA, 1);
        oA += __shfl_xor_sync(0xffffffffu, oA, 2);
        oB += __shfl_xor_sync(0xffffffffu, oB, 1);
        oB += __shfl_xor_sync(0xffffffffu, oB, 2);
        if (tig == 0) {
            int row = wm * 32 + mt * 16 + gid;
            sRed[wn * 128 + row] = oA;
            sRed[wn * 128 + row + 8] = oB;
        }
    }
    __syncthreads();
    if (t < 128 && pt0 + t < nTot)
        out[pt0 + t] = sEx[4] + sRed[t] + sRed[128 + t]
                               + sRed[256 + t] + sRed[384 + t];
}

// ---------------------------------------------------------------------------
extern "C" void kernel_launch(void* const* d_in, const int* in_sizes, int n_in,
                              void* d_out, int out_size)
{
    const float* coords = (const float*)d_in[0];
    const float* W0 = (const float*)d_in[1];
    const float* W1 = (const float*)d_in[3];
    const float* W2 = (const float*)d_in[5];
    float* out = (float*)d_out;

    int n = in_sizes[0] / 3;
    prep_kernel<<<160, 256>>>(W0, W1, W2);
    cudaFuncSetAttribute(mlp3d_main,
                         cudaFuncAttributeMaxDynamicSharedMemorySize,
                         SMEM_BYTES);
    mlp3d_main<<<(n + 127) / 128, 512, SMEM_BYTES>>>(
        coords, (const float*)d_in[2], (const float*)d_in[4],
        (const float*)d_in[6], (const float*)d_in[7], (const float*)d_in[8],
        (const float*)d_in[9], (const float*)d_in[10], out, n);
}